// round 5
// baseline (speedup 1.0000x reference)
#include <cuda_runtime.h>
#include <cstdint>

#define NT      215     // number of (l1,l2,l) triples
#define NCOEF   81      // (LMAX+1)^2
#define TPB     256     // threads per CTA = batch rows per CTA
#define XS      257     // padded row stride of transposed x tile (odd -> conflict-free)
#define XT_FL   20820   // 81*257 = 20817, rounded up to multiple of 4 floats (16B align)
#define MAXC    5780    // 17*17*20 floats: max padded compact C block
#define CHUNK   5       // output staging chunk (215 = 5*43)

static_assert(NT % CHUNK == 0, "chunk must divide NT");

// ---------------------------------------------------------------------------
// helpers
// ---------------------------------------------------------------------------
__device__ __forceinline__ unsigned smem_addr_u32(const void* p) {
    unsigned r;
    asm("{ .reg .u64 t; cvta.to.shared.u64 t, %1; cvt.u32.u64 %0, t; }"
        : "=r"(r) : "l"(p));
    return r;
}

__device__ __forceinline__ void cp_async4(unsigned dst, const float* src) {
    asm volatile("cp.async.ca.shared.global [%0], [%1], 4;" :: "r"(dst), "l"(src));
}

__device__ __forceinline__ void cp_commit() {
    asm volatile("cp.async.commit_group;" ::: "memory");
}

__device__ __forceinline__ void cp_wait_all() {
    asm volatile("cp.async.wait_group 0;" ::: "memory");
}

// ---------------------------------------------------------------------------
// Per-triple contraction, templated on d3 so packed-F3 stays in registers.
//   beta = sum_{i<d1, j<d2, k<D3} C[i][j][k] * F1[i] * F2[j] * F3[k]
// C staged in smem with each (i,j) row padded to P4*4 floats; padded C slots
// may hold stale (finite) garbage — the matching F3 pack halves are 0.0f so
// they contribute exactly 0.
// ---------------------------------------------------------------------------
template<int D3>
__device__ __forceinline__ float compute_triple(const float* xT, const float* Cs,
                                                int l1s, int l2s, int ls,
                                                int d1, int d2, int tid)
{
    constexpr int P4 = (D3 + 3) / 4;   // float4 groups per row
    constexpr int NP = 2 * P4;         // f32x2 packs per row

    // Packed F3 (zero-padded past D3)
    unsigned long long f3p[NP];
#pragma unroll
    for (int q = 0; q < NP; q++) {
        float lo = (2 * q     < D3) ? xT[(ls + 2 * q    ) * XS + tid] : 0.0f;
        float hi = (2 * q + 1 < D3) ? xT[(ls + 2 * q + 1) * XS + tid] : 0.0f;
        asm("mov.b64 %0, {%1, %2};" : "=l"(f3p[q]) : "f"(lo), "f"(hi));
    }

    unsigned long long acc2 = 0ULL;
    const float4* crow = (const float4*)Cs;
    const float*  p1   = xT + l1s * XS + tid;

    for (int i = 0; i < d1; i++, p1 += XS) {
        float f1 = *p1;
        const float* p2 = xT + l2s * XS + tid;
        for (int j = 0; j < d2; j++, p2 += XS) {
            float f12 = f1 * (*p2);
            unsigned long long f12d;
            asm("mov.b64 %0, {%1, %1};" : "=l"(f12d) : "f"(f12));

            unsigned long long sa = 0ULL, sb = 0ULL;
#pragma unroll
            for (int q = 0; q < P4; q++) {
                float4 c4 = crow[q];               // LDS.128, broadcast across lanes
                unsigned long long c01, c23;
                asm("mov.b64 %0, {%1, %2};" : "=l"(c01) : "f"(c4.x), "f"(c4.y));
                asm("mov.b64 %0, {%1, %2};" : "=l"(c23) : "f"(c4.z), "f"(c4.w));
                asm("fma.rn.f32x2 %0, %1, %2, %0;" : "+l"(sa) : "l"(c01), "l"(f3p[2 * q]));
                asm("fma.rn.f32x2 %0, %1, %2, %0;" : "+l"(sb) : "l"(c23), "l"(f3p[2 * q + 1]));
            }
            crow += P4;
            asm("fma.rn.f32x2 %0, %1, %2, %0;" : "+l"(acc2) : "l"(sa), "l"(f12d));
            asm("fma.rn.f32x2 %0, %1, %2, %0;" : "+l"(acc2) : "l"(sb), "l"(f12d));
        }
    }

    float alo, ahi;
    asm("mov.b64 {%0, %1}, %2;" : "=f"(alo), "=f"(ahi) : "l"(acc2));
    return alo + ahi;
}

// ---------------------------------------------------------------------------
// Stage compact C block of triple t into smem buffer (row-padded-to-4 layout)
// via 4-byte cp.async. i,j,k recovered from flat index with magic-multiply
// division. BUG FIX vs previous round: for d3==1 (and d23==1) the magic
// constant ceil(2^32/d) == 2^32 truncates to 0 in 32 bits, which silently
// produced j=0,k=rem and scattered the 9 diagonal (l,l,0) triples into the
// padding slots. Those divisors are handled explicitly now (uniform branch,
// no divergence).
// ---------------------------------------------------------------------------
__device__ __forceinline__ void stage_triple(int t, float* buf, const float* cg,
                                             const int* tb_d1, const int* tb_d2,
                                             const int* tb_d3,
                                             const unsigned* tb_m23,
                                             const unsigned* tb_m3, int tid)
{
    int d2  = tb_d2[t], d3 = tb_d3[t];
    int d23 = d2 * d3;
    int total = tb_d1[t] * d23;
    unsigned m23 = tb_m23[t], m3 = tb_m3[t];
    int p4f = (d3 + 3) & ~3;
    const float* src = cg + (size_t)t * (17 * 17 * 17);
    unsigned sbase = smem_addr_u32(buf);

    bool d23_one = (d23 == 1);
    bool d3_one  = (d3 == 1);

    for (int e = tid; e < total; e += TPB) {
        int i   = d23_one ? e : (int)__umulhi((unsigned)e, m23);
        int rem = e - i * d23;
        int j   = d3_one ? rem : (int)__umulhi((unsigned)rem, m3);
        int k   = rem - j * d3;
        unsigned dst = sbase + (unsigned)(((i * d2 + j) * p4f + k) << 2);
        cp_async4(dst, src + i * 289 + j * 17 + k);
    }
}

// ---------------------------------------------------------------------------
// Main kernel
// ---------------------------------------------------------------------------
extern __shared__ char smem_raw[];

__global__ void __launch_bounds__(TPB, 1)
bispec_kernel(const float* __restrict__ x, const float* __restrict__ cg,
              float* __restrict__ out, int B)
{
    float* xT  = (float*)smem_raw;          // [81][257] transposed x tile
    float* cb0 = xT + XT_FL;                // C double buffer
    float* cb1 = cb0 + MAXC;
    float* ob  = cb1 + MAXC;                // [TPB][CHUNK] output staging
    int*   tb  = (int*)(ob + CHUNK * TPB);  // triple table (8 arrays of NT)
    int* tb_l1s = tb;
    int* tb_l2s = tb + NT;
    int* tb_ls  = tb + 2 * NT;
    int* tb_d1  = tb + 3 * NT;
    int* tb_d2  = tb + 4 * NT;
    int* tb_d3  = tb + 5 * NT;
    unsigned* tb_m23 = (unsigned*)(tb + 6 * NT);
    unsigned* tb_m3  = (unsigned*)(tb + 7 * NT);

    const int tid = threadIdx.x;
    const int b0  = blockIdx.x * TPB;

    // Build triple table (must match reference enumeration order)
    if (tid == 0) {
        int n = 0;
        for (int l1 = 0; l1 <= 8; l1++)
            for (int l2 = l1; l2 <= 8; l2++) {
                int lhi = (l1 + l2 < 8) ? (l1 + l2) : 8;
                for (int l = l2 - l1; l <= lhi; l++) {
                    tb_l1s[n] = l1 * l1; tb_l2s[n] = l2 * l2; tb_ls[n] = l * l;
                    int d1 = 2 * l1 + 1, d2 = 2 * l2 + 1, d3 = 2 * l + 1;
                    tb_d1[n] = d1; tb_d2[n] = d2; tb_d3[n] = d3;
                    unsigned d23 = (unsigned)(d2 * d3);
                    // NOTE: for divisor 1 these truncate to 0 — stage_triple
                    // branches those cases and never uses the magic there.
                    tb_m23[n] = (unsigned)((0x100000000ULL + d23 - 1) / d23);
                    tb_m3[n]  = (unsigned)((0x100000000ULL + (unsigned)d3 - 1) / (unsigned)d3);
                    n++;
                }
            }
    }

    // Zero C buffers once (pad slots must start finite; stale data later is finite too)
    for (int i = tid; i < 2 * MAXC; i += TPB) cb0[i] = 0.0f;

    // Stage x tile transposed: xT[c][r] = x[b0+r][c]; coalesced global reads,
    // conflict-free smem writes (stride 257).
    for (int idx = tid; idx < NCOEF * TPB; idx += TPB) {
        int r = idx / NCOEF;            // const divisor -> magic multiply
        int c = idx - r * NCOEF;
        float v = (b0 + r < B) ? x[(size_t)b0 * NCOEF + idx] : 0.0f;
        xT[c * XS + r] = v;
    }
    __syncthreads();   // table + zeros + xT visible

    // Prime the C pipeline
    stage_triple(0, cb0, cg, tb_d1, tb_d2, tb_d3, tb_m23, tb_m3, tid);
    cp_commit();
    cp_wait_all();
    __syncthreads();

    int tmod = 0, tbase = 0;
    for (int t = 0; t < NT; t++) {
        float* cur = (t & 1) ? cb1 : cb0;
        float* nxt = (t & 1) ? cb0 : cb1;

        // Prefetch next triple's C while computing this one
        if (t + 1 < NT)
            stage_triple(t + 1, nxt, cg, tb_d1, tb_d2, tb_d3, tb_m23, tb_m3, tid);
        cp_commit();

        int l1s = tb_l1s[t], l2s = tb_l2s[t], ls = tb_ls[t];
        int d1 = tb_d1[t], d2 = tb_d2[t], d3 = tb_d3[t];

        float acc = 0.0f;
        switch (d3) {
            case 1:  acc = compute_triple< 1>(xT, cur, l1s, l2s, ls, d1, d2, tid); break;
            case 3:  acc = compute_triple< 3>(xT, cur, l1s, l2s, ls, d1, d2, tid); break;
            case 5:  acc = compute_triple< 5>(xT, cur, l1s, l2s, ls, d1, d2, tid); break;
            case 7:  acc = compute_triple< 7>(xT, cur, l1s, l2s, ls, d1, d2, tid); break;
            case 9:  acc = compute_triple< 9>(xT, cur, l1s, l2s, ls, d1, d2, tid); break;
            case 11: acc = compute_triple<11>(xT, cur, l1s, l2s, ls, d1, d2, tid); break;
            case 13: acc = compute_triple<13>(xT, cur, l1s, l2s, ls, d1, d2, tid); break;
            case 15: acc = compute_triple<15>(xT, cur, l1s, l2s, ls, d1, d2, tid); break;
            default: acc = compute_triple<17>(xT, cur, l1s, l2s, ls, d1, d2, tid); break;
        }
        ob[tid * CHUNK + tmod] = acc;   // stride 5 (odd*4B) -> conflict-free

        cp_wait_all();
        __syncthreads();                // next C buffer ready; ob writes visible

        if (++tmod == CHUNK) {
            // Coalesced-ish flush: consecutive threads cover consecutive
            // (b, t) pairs with t fastest -> 20B contiguous runs per row.
            for (int idx = tid; idx < CHUNK * TPB; idx += TPB) {
                int bb = (idx * 6554) >> 15;      // idx / 5, exact for idx < 1280
                int j  = idx - bb * CHUNK;
                int b  = b0 + bb;
                if (b < B) out[(size_t)b * NT + tbase + j] = ob[idx];
            }
            __syncthreads();            // protect ob reuse
            tmod = 0;
            tbase += CHUNK;
        }
    }
}

// ---------------------------------------------------------------------------
// Entry point
// ---------------------------------------------------------------------------
extern "C" void kernel_launch(void* const* d_in, const int* in_sizes, int n_in,
                              void* d_out, int out_size)
{
    const float* x  = (const float*)d_in[0];
    const float* cg = (const float*)d_in[1];
    float* out = (float*)d_out;

    int B = in_sizes[0] / NCOEF;
    int grid = (B + TPB - 1) / TPB;

    size_t smem_bytes = (size_t)(XT_FL + 2 * MAXC + CHUNK * TPB) * sizeof(float)
                      + (size_t)8 * NT * sizeof(int);   // = 141520 B

    cudaFuncSetAttribute(bispec_kernel,
                         cudaFuncAttributeMaxDynamicSharedMemorySize,
                         (int)smem_bytes);

    bispec_kernel<<<grid, TPB, smem_bytes>>>(x, cg, out, B);
}

// round 6
// speedup vs baseline: 1.4786x; 1.4786x over previous
#include <cuda_runtime.h>
#include <cstdint>

#define NT      215     // number of (l1,l2,l) triples
#define NCOEF   81      // (LMAX+1)^2
#define TPB     256     // threads per CTA
#define ROWS    512     // batch rows per CTA = 2*TPB (R=2 register blocking)
#define XS      513     // padded row stride of transposed x tile (513%32==1 -> conflict-free staging)
#define XT_FL   41556   // 81*513 = 41553, rounded up to multiple of 4 floats
#define MAXC    5780    // 17*17*20 floats: max padded compact C block

// ---------------------------------------------------------------------------
// helpers
// ---------------------------------------------------------------------------
__device__ __forceinline__ unsigned smem_addr_u32(const void* p) {
    unsigned r;
    asm("{ .reg .u64 t; cvta.to.shared.u64 t, %1; cvt.u32.u64 %0, t; }"
        : "=r"(r) : "l"(p));
    return r;
}

__device__ __forceinline__ void cp_async4(unsigned dst, const float* src) {
    asm volatile("cp.async.ca.shared.global [%0], [%1], 4;" :: "r"(dst), "l"(src));
}

__device__ __forceinline__ void cp_commit() {
    asm volatile("cp.async.commit_group;" ::: "memory");
}

__device__ __forceinline__ void cp_wait_all() {
    asm volatile("cp.async.wait_group 0;" ::: "memory");
}

#define FMA2(acc, a, b) asm("fma.rn.f32x2 %0, %1, %2, %0;" : "+l"(acc) : "l"(a), "l"(b))
#define PACK2(d, lo, hi) asm("mov.b64 %0, {%1, %2};" : "=l"(d) : "f"(lo), "f"(hi))
#define DUP2(d, v)       asm("mov.b64 %0, {%1, %1};" : "=l"(d) : "f"(v))

// ---------------------------------------------------------------------------
// Per-triple contraction for TWO batch rows per thread (R=2).
//   beta = sum_{i<d1, j<d2, k<D3} C[i][j][k] * F1[i] * F2[j] * F3[k]
// C staged in smem, each (i,j) row padded to P4*4 floats. Padded C slots may
// hold stale *finite* values (previous cg floats / initial zeros) — the
// matching F3 pack halves are 0.0f so they contribute exactly 0.
// Each broadcast LDS.128 of C feeds 4 FFMA2 (2 rows x 2 packs) -> LDS:FMA
// ratio halved vs the R=1 version.
// ---------------------------------------------------------------------------
template<int D3>
__device__ __forceinline__ void compute_triple2(const float* xT, const float* Cs,
                                                int l1s, int l2s, int ls,
                                                int d1, int d2, int tid,
                                                float& out_a, float& out_b)
{
    constexpr int P4 = (D3 + 3) / 4;   // float4 groups per C row
    constexpr int NP = 2 * P4;         // f32x2 packs per C row

    // Packed F3 for both rows (zero-padded past D3)
    unsigned long long fa[NP], fb[NP];
#pragma unroll
    for (int q = 0; q < NP; q++) {
        const float* base0 = xT + (ls + 2 * q) * XS + tid;
        float a0 = (2 * q     < D3) ? base0[0]        : 0.0f;
        float a1 = (2 * q + 1 < D3) ? base0[XS]       : 0.0f;
        float b0 = (2 * q     < D3) ? base0[TPB]      : 0.0f;
        float b1 = (2 * q + 1 < D3) ? base0[XS + TPB] : 0.0f;
        PACK2(fa[q], a0, a1);
        PACK2(fb[q], b0, b1);
    }

    unsigned long long acc_a = 0ULL, acc_b = 0ULL;
    const float4* crow = (const float4*)Cs;
    const float*  p1   = xT + l1s * XS + tid;

    for (int i = 0; i < d1; i++, p1 += XS) {
        float f1a = p1[0];
        float f1b = p1[TPB];
        const float* p2 = xT + l2s * XS + tid;
        for (int j = 0; j < d2; j++, p2 += XS) {
            float f12a = f1a * p2[0];
            float f12b = f1b * p2[TPB];
            unsigned long long f12ad, f12bd;
            DUP2(f12ad, f12a);
            DUP2(f12bd, f12b);

            unsigned long long sa_a = 0ULL, sb_a = 0ULL;
            unsigned long long sa_b = 0ULL, sb_b = 0ULL;
#pragma unroll
            for (int q = 0; q < P4; q++) {
                float4 c4 = crow[q];               // LDS.128 broadcast
                unsigned long long c01, c23;
                PACK2(c01, c4.x, c4.y);
                PACK2(c23, c4.z, c4.w);
                FMA2(sa_a, c01, fa[2 * q]);
                FMA2(sa_b, c01, fb[2 * q]);
                FMA2(sb_a, c23, fa[2 * q + 1]);
                FMA2(sb_b, c23, fb[2 * q + 1]);
            }
            crow += P4;
            FMA2(acc_a, sa_a, f12ad);
            FMA2(acc_a, sb_a, f12ad);
            FMA2(acc_b, sa_b, f12bd);
            FMA2(acc_b, sb_b, f12bd);
        }
    }

    float alo, ahi, blo, bhi;
    asm("mov.b64 {%0, %1}, %2;" : "=f"(alo), "=f"(ahi) : "l"(acc_a));
    asm("mov.b64 {%0, %1}, %2;" : "=f"(blo), "=f"(bhi) : "l"(acc_b));
    out_a = alo + ahi;
    out_b = blo + bhi;
}

// ---------------------------------------------------------------------------
// Stage compact C block of triple t into smem (rows padded to 4 floats) via
// 4-byte cp.async. Magic-multiply division; divisor==1 cases (where the magic
// ceil(2^32/d) truncates to 0) handled by uniform branch.
// ---------------------------------------------------------------------------
__device__ __forceinline__ void stage_triple(int t, float* buf, const float* cg,
                                             const int* tb_d1, const int* tb_d2,
                                             const int* tb_d3,
                                             const unsigned* tb_m23,
                                             const unsigned* tb_m3, int tid)
{
    int d2  = tb_d2[t], d3 = tb_d3[t];
    int d23 = d2 * d3;
    int total = tb_d1[t] * d23;
    unsigned m23 = tb_m23[t], m3 = tb_m3[t];
    int p4f = (d3 + 3) & ~3;
    const float* src = cg + (size_t)t * (17 * 17 * 17);
    unsigned sbase = smem_addr_u32(buf);

    bool d23_one = (d23 == 1);
    bool d3_one  = (d3 == 1);

    for (int e = tid; e < total; e += TPB) {
        int i   = d23_one ? e : (int)__umulhi((unsigned)e, m23);
        int rem = e - i * d23;
        int j   = d3_one ? rem : (int)__umulhi((unsigned)rem, m3);
        int k   = rem - j * d3;
        unsigned dst = sbase + (unsigned)(((i * d2 + j) * p4f + k) << 2);
        cp_async4(dst, src + i * 289 + j * 17 + k);
    }
}

// ---------------------------------------------------------------------------
// Main kernel
// ---------------------------------------------------------------------------
extern __shared__ char smem_raw[];

__global__ void __launch_bounds__(TPB, 1)
bispec_kernel(const float* __restrict__ x, const float* __restrict__ cg,
              float* __restrict__ out, int B)
{
    float* xT  = (float*)smem_raw;          // [81][513] transposed x tile (512 rows)
    float* cb0 = xT + XT_FL;                // C double buffer
    float* cb1 = cb0 + MAXC;
    int*   tb  = (int*)(cb1 + MAXC);        // triple table (8 arrays of NT)
    int* tb_l1s = tb;
    int* tb_l2s = tb + NT;
    int* tb_ls  = tb + 2 * NT;
    int* tb_d1  = tb + 3 * NT;
    int* tb_d2  = tb + 4 * NT;
    int* tb_d3  = tb + 5 * NT;
    unsigned* tb_m23 = (unsigned*)(tb + 6 * NT);
    unsigned* tb_m3  = (unsigned*)(tb + 7 * NT);

    const int tid = threadIdx.x;
    const int b0  = blockIdx.x * ROWS;

    // Build triple table (must match reference enumeration order)
    if (tid == 0) {
        int n = 0;
        for (int l1 = 0; l1 <= 8; l1++)
            for (int l2 = l1; l2 <= 8; l2++) {
                int lhi = (l1 + l2 < 8) ? (l1 + l2) : 8;
                for (int l = l2 - l1; l <= lhi; l++) {
                    tb_l1s[n] = l1 * l1; tb_l2s[n] = l2 * l2; tb_ls[n] = l * l;
                    int d1 = 2 * l1 + 1, d2 = 2 * l2 + 1, d3 = 2 * l + 1;
                    tb_d1[n] = d1; tb_d2[n] = d2; tb_d3[n] = d3;
                    unsigned d23 = (unsigned)(d2 * d3);
                    // divisor==1 -> magic truncates to 0; stage_triple branches that case
                    tb_m23[n] = (unsigned)((0x100000000ULL + d23 - 1) / d23);
                    tb_m3[n]  = (unsigned)((0x100000000ULL + (unsigned)d3 - 1) / (unsigned)d3);
                    n++;
                }
            }
    }

    // Zero C buffers once (pad slots must start finite; stale data later is
    // finite cg floats, nullified by zero F3 pack halves)
    for (int i = tid; i < 2 * MAXC; i += TPB) cb0[i] = 0.0f;

    // Stage x tile transposed: xT[c][r] = x[b0+r][c]; coalesced global reads,
    // conflict-free smem writes (stride 513 -> consecutive banks).
    for (int idx = tid; idx < NCOEF * ROWS; idx += TPB) {
        int r = idx / NCOEF;            // const divisor -> magic multiply
        int c = idx - r * NCOEF;
        float v = (b0 + r < B) ? x[(size_t)b0 * NCOEF + idx] : 0.0f;
        xT[c * XS + r] = v;
    }
    __syncthreads();   // table + zeros + xT visible

    // Prime the C pipeline
    stage_triple(0, cb0, cg, tb_d1, tb_d2, tb_d3, tb_m23, tb_m3, tid);
    cp_commit();
    cp_wait_all();
    __syncthreads();

    const size_t ob_a = (size_t)(b0 + tid)       * NT;
    const size_t ob_b = (size_t)(b0 + tid + TPB) * NT;
    const bool va = (b0 + tid       < B);
    const bool vb = (b0 + tid + TPB < B);

    for (int t = 0; t < NT; t++) {
        float* cur = (t & 1) ? cb1 : cb0;
        float* nxt = (t & 1) ? cb0 : cb1;

        // Prefetch next triple's C while computing this one
        if (t + 1 < NT)
            stage_triple(t + 1, nxt, cg, tb_d1, tb_d2, tb_d3, tb_m23, tb_m3, tid);
        cp_commit();

        int l1s = tb_l1s[t], l2s = tb_l2s[t], ls = tb_ls[t];
        int d1 = tb_d1[t], d2 = tb_d2[t], d3 = tb_d3[t];

        float acc_a = 0.0f, acc_b = 0.0f;
        switch (d3) {
            case 1:  compute_triple2< 1>(xT, cur, l1s, l2s, ls, d1, d2, tid, acc_a, acc_b); break;
            case 3:  compute_triple2< 3>(xT, cur, l1s, l2s, ls, d1, d2, tid, acc_a, acc_b); break;
            case 5:  compute_triple2< 5>(xT, cur, l1s, l2s, ls, d1, d2, tid, acc_a, acc_b); break;
            case 7:  compute_triple2< 7>(xT, cur, l1s, l2s, ls, d1, d2, tid, acc_a, acc_b); break;
            case 9:  compute_triple2< 9>(xT, cur, l1s, l2s, ls, d1, d2, tid, acc_a, acc_b); break;
            case 11: compute_triple2<11>(xT, cur, l1s, l2s, ls, d1, d2, tid, acc_a, acc_b); break;
            case 13: compute_triple2<13>(xT, cur, l1s, l2s, ls, d1, d2, tid, acc_a, acc_b); break;
            case 15: compute_triple2<15>(xT, cur, l1s, l2s, ls, d1, d2, tid, acc_a, acc_b); break;
            default: compute_triple2<17>(xT, cur, l1s, l2s, ls, d1, d2, tid, acc_a, acc_b); break;
        }

        // Direct scattered stores: 4B @ stride 860B. ~900MB of L2 sector
        // traffic over the whole kernel (~75us at LTS cap) — hidden under
        // >2ms of compute; not worth a smem staging buffer at this smem budget.
        if (va) out[ob_a + t] = acc_a;
        if (vb) out[ob_b + t] = acc_b;

        cp_wait_all();
        __syncthreads();                // next C buffer fully staged
    }
}

// ---------------------------------------------------------------------------
// Entry point
// ---------------------------------------------------------------------------
extern "C" void kernel_launch(void* const* d_in, const int* in_sizes, int n_in,
                              void* d_out, int out_size)
{
    const float* x  = (const float*)d_in[0];
    const float* cg = (const float*)d_in[1];
    float* out = (float*)d_out;

    int B = in_sizes[0] / NCOEF;
    int grid = (B + ROWS - 1) / ROWS;

    size_t smem_bytes = (size_t)(XT_FL + 2 * MAXC) * sizeof(float)
                      + (size_t)8 * NT * sizeof(int);   // = 219,344 B

    cudaFuncSetAttribute(bispec_kernel,
                         cudaFuncAttributeMaxDynamicSharedMemorySize,
                         (int)smem_bytes);

    bispec_kernel<<<grid, TPB, smem_bytes>>>(x, cg, out, B);
}